// round 1
// baseline (speedup 1.0000x reference)
#include <cuda_runtime.h>

// GaussianBlur2D: depthwise 11x11 Gaussian blur, reflect padding,
// x: (16, 64, 512, 512) fp32, sigma: (1,) fp32.
// Separable implementation: g[i][j] = (h[i]/S) * (h[j]/S) with S = sum(h),
// identical in value to reference's 2D-normalized kernel.

#define KS   11
#define PAD  5
#define TW   128
#define TH   32
#define IMG_H 512
#define IMG_W 512

__device__ float g_w[KS];

// Prologue: compute normalized 1D Gaussian weights from device-resident sigma.
__global__ void compute_weights_kernel(const float* __restrict__ sigma) {
    if (threadIdx.x == 0) {
        float s = fabsf(sigma[0]) + 1e-6f;
        float inv = 1.0f / (2.0f * s * s);
        float h[KS];
        float sum = 0.0f;
        #pragma unroll
        for (int j = 0; j < KS; j++) {
            float r = (float)j - (float)(KS - 1) * 0.5f;
            h[j] = __expf(-r * r * inv);
            sum += h[j];
        }
        float rs = 1.0f / sum;
        #pragma unroll
        for (int j = 0; j < KS; j++) g_w[j] = h[j] * rs;
    }
}

__device__ __forceinline__ int reflect_idx(int i, int n) {
    // reflect mode (no edge repeat): -1 -> 1, n -> n-2. PAD < n so one fold suffices.
    i = (i < 0) ? -i : i;
    i = (i >= n) ? (2 * n - 2 - i) : i;
    return i;
}

__global__ __launch_bounds__(256, 4)
void gaussian_blur_kernel(const float* __restrict__ in, float* __restrict__ out) {
    // 42 x 138 input tile, 32 x 138 vertically-blurred tile
    __shared__ float s_in[TH + 2 * PAD][TW + 2 * PAD];
    __shared__ float s_v [TH][TW + 2 * PAD];
    __shared__ float s_w [KS];

    const int tid = threadIdx.x;
    const int tx  = tid & 31;
    const int ty  = tid >> 5;          // 32 x 8 thread layout

    if (tid < KS) s_w[tid] = g_w[tid];

    const int x0 = blockIdx.x * TW;
    const int y0 = blockIdx.y * TH;
    const size_t img_off = (size_t)blockIdx.z * (size_t)(IMG_H * IMG_W);
    const float* img  = in  + img_off;
    float*       oimg = out + img_off;

    // ---- load halo tile with reflect padding ----
    #pragma unroll
    for (int r = ty; r < TH + 2 * PAD; r += 8) {
        int gy = reflect_idx(y0 + r - PAD, IMG_H);
        const float* row = img + (size_t)gy * IMG_W;
        #pragma unroll
        for (int c = tx; c < TW + 2 * PAD; c += 32) {
            int gx = reflect_idx(x0 + c - PAD, IMG_W);
            s_in[r][c] = row[gx];
        }
    }
    __syncthreads();

    float w[KS];
    #pragma unroll
    for (int j = 0; j < KS; j++) w[j] = s_w[j];

    // ---- vertical 1D pass (over full halo width) ----
    #pragma unroll
    for (int r = ty; r < TH; r += 8) {
        #pragma unroll
        for (int c = tx; c < TW + 2 * PAD; c += 32) {
            float acc = 0.0f;
            #pragma unroll
            for (int i = 0; i < KS; i++)
                acc = fmaf(w[i], s_in[r + i][c], acc);
            s_v[r][c] = acc;
        }
    }
    __syncthreads();

    // ---- horizontal 1D pass + coalesced store ----
    #pragma unroll
    for (int r = ty; r < TH; r += 8) {
        float* orow = oimg + (size_t)(y0 + r) * IMG_W + x0;
        #pragma unroll
        for (int c = tx; c < TW; c += 32) {
            float acc = 0.0f;
            #pragma unroll
            for (int j = 0; j < KS; j++)
                acc = fmaf(w[j], s_v[r][c + j], acc);
            orow[c] = acc;
        }
    }
}

extern "C" void kernel_launch(void* const* d_in, const int* in_sizes, int n_in,
                              void* d_out, int out_size) {
    const float* x     = (const float*)d_in[0];
    const float* sigma = (const float*)d_in[1];
    float*       out   = (float*)d_out;

    // number of (B*C) image planes
    int n_img = in_sizes[0] / (IMG_H * IMG_W);

    compute_weights_kernel<<<1, 32>>>(sigma);

    dim3 grid(IMG_W / TW, IMG_H / TH, n_img);
    gaussian_blur_kernel<<<grid, 256>>>(x, out);
}

// round 2
// speedup vs baseline: 2.2062x; 2.2062x over previous
#include <cuda_runtime.h>

// GaussianBlur2D: depthwise 11x11 Gaussian blur, reflect padding.
// x: (16, 64, 512, 512) fp32, sigma: (1,) fp32.
// Separable streaming implementation:
//   - vertical 11-tap entirely in registers (14-row sliding float4 window)
//   - horizontal 11-tap via one smem row (with mirrored halo), aligned LDS.128
// g2d[i][j] = (h[i]/S)*(h[j]/S) with S = sum(h)  == reference's 2D-normalized kernel.

#define KS    11
#define IMG   512
#define NT    128      // threads per block; NT*4 == IMG (one full row per block)
#define RPT   4        // output rows produced per loop iteration
#define STRIP 128      // rows per block
#define SVW   528      // padded smem row width (need 522 = 512 + 2*5)

__device__ float g_w[KS];

__global__ void compute_weights_kernel(const float* __restrict__ sigma) {
    if (threadIdx.x == 0) {
        float s = fabsf(sigma[0]) + 1e-6f;
        float inv = 1.0f / (2.0f * s * s);
        float h[KS];
        float sum = 0.0f;
        #pragma unroll
        for (int j = 0; j < KS; j++) {
            float r = (float)j - (float)(KS - 1) * 0.5f;
            h[j] = __expf(-r * r * inv);
            sum += h[j];
        }
        float rs = 1.0f / sum;
        #pragma unroll
        for (int j = 0; j < KS; j++) g_w[j] = h[j] * rs;
    }
}

__device__ __forceinline__ int refl(int i) {
    i = (i < 0) ? -i : i;
    return (i >= IMG) ? (2 * IMG - 2 - i) : i;
}

__global__ __launch_bounds__(NT, 4)
void gaussian_blur_kernel(const float* __restrict__ in, float* __restrict__ out) {
    // s_v[r][j] holds vblur at x = j - 5 (j in [0, 521]), halo filled by mirroring.
    __shared__ float s_v[RPT][SVW];

    const int t = threadIdx.x;
    const int x = t << 2;                       // this thread owns columns x..x+3
    const int plane = blockIdx.x >> 2;
    const int y0 = (blockIdx.x & 3) * STRIP;
    const float* __restrict__ img  = in  + (size_t)plane * (IMG * IMG);
    float*       __restrict__ oimg = out + (size_t)plane * (IMG * IMG);

    float w[KS];
    #pragma unroll
    for (int i = 0; i < KS; i++) w[i] = g_w[i];

    // Sliding window: win[k] = input row (ybase + k - 5), k = 0..13,
    // covering rows needed for outputs ybase .. ybase+3.
    float4 win[RPT + KS - 1 + RPT - 1 - (RPT - 1)]; // = 14
    #pragma unroll
    for (int k = 0; k < 14; k++)
        win[k] = *(const float4*)(img + (size_t)refl(y0 + k - 5) * IMG + x);

    for (int yb = 0; yb < STRIP; yb += RPT) {
        const int y = y0 + yb;

        // Prefetch the next RPT input rows (rows y+9 .. y+12).
        float4 pre[RPT];
        #pragma unroll
        for (int k = 0; k < RPT; k++)
            pre[k] = *(const float4*)(img + (size_t)refl(y + 9 + k) * IMG + x);

        // ---- vertical pass (registers only) ----
        #pragma unroll
        for (int r = 0; r < RPT; r++) {
            float a[4] = {0.f, 0.f, 0.f, 0.f};
            #pragma unroll
            for (int i = 0; i < KS; i++) {
                const float  wi = w[i];
                const float4 v  = win[r + i];
                a[0] = fmaf(wi, v.x, a[0]);
                a[1] = fmaf(wi, v.y, a[1]);
                a[2] = fmaf(wi, v.z, a[2]);
                a[3] = fmaf(wi, v.w, a[3]);
            }
            float* sv = s_v[r];
            #pragma unroll
            for (int c = 0; c < 4; c++) {
                const int xc = x + c;
                sv[5 + xc] = a[c];
                // reflected halo: x' = -5..-1  -> x = 5..1 ; x' = 512..516 -> x = 510..506
                if (xc >= 1   && xc <= 5)   sv[5 - xc]    = a[c];
                if (xc >= 506 && xc <= 510) sv[1027 - xc] = a[c];
            }
        }
        __syncthreads();

        // ---- horizontal pass: 4 aligned LDS.128 -> 4 outputs per row ----
        #pragma unroll
        for (int r = 0; r < RPT; r++) {
            const float4* vp = (const float4*)&s_v[r][x];
            const float4 A = vp[0], B = vp[1], C = vp[2], D = vp[3];
            const float v[16] = {A.x, A.y, A.z, A.w,
                                 B.x, B.y, B.z, B.w,
                                 C.x, C.y, C.z, C.w,
                                 D.x, D.y, D.z, D.w};
            float o0 = 0.f, o1 = 0.f, o2 = 0.f, o3 = 0.f;
            #pragma unroll
            for (int j = 0; j < KS; j++) {
                const float wj = w[j];
                o0 = fmaf(wj, v[j],     o0);
                o1 = fmaf(wj, v[j + 1], o1);
                o2 = fmaf(wj, v[j + 2], o2);
                o3 = fmaf(wj, v[j + 3], o3);
            }
            *(float4*)(oimg + (size_t)(y + r) * IMG + x) = make_float4(o0, o1, o2, o3);
        }
        __syncthreads();

        // ---- slide the window down by RPT rows ----
        #pragma unroll
        for (int k = 0; k < 14 - RPT; k++) win[k] = win[k + RPT];
        #pragma unroll
        for (int k = 0; k < RPT; k++)      win[10 + k] = pre[k];
    }
}

extern "C" void kernel_launch(void* const* d_in, const int* in_sizes, int n_in,
                              void* d_out, int out_size) {
    const float* x     = (const float*)d_in[0];
    const float* sigma = (const float*)d_in[1];
    float*       out   = (float*)d_out;

    const int n_img = in_sizes[0] / (IMG * IMG);   // B*C planes

    compute_weights_kernel<<<1, 32>>>(sigma);

    const int strips = IMG / STRIP;                // 4
    gaussian_blur_kernel<<<n_img * strips, NT>>>(x, out);
}